// round 1
// baseline (speedup 1.0000x reference)
#include <cuda_runtime.h>
#include <cstdint>

#define N_MAX 50000
#define D 128

// Scratch (no cudaMalloc allowed)
__device__ float g_agg[N_MAX * D];        // scatter accumulator [N,128]
__device__ int   g_deg_out[N_MAX];
__device__ int   g_deg_in[N_MAX];
__device__ float g_Wfused[D * D];         // W_conv @ W_aggr[0:128]
__device__ float g_bias[D];               // b_conv @ Wa1 + b_aggr

// ---------------------------------------------------------------------------
// K0: zero agg + degree counters
__global__ void zero_kernel(int n) {
    int i = blockIdx.x * blockDim.x + threadIdx.x;
    int nf4 = n * (D / 4);
    if (i < nf4) ((float4*)g_agg)[i] = make_float4(0.f, 0.f, 0.f, 0.f);
    if (i < n) { g_deg_out[i] = 0; g_deg_in[i] = 0; }
}

// K1: degree histogram
__global__ void deg_kernel(const int* __restrict__ src,
                           const int* __restrict__ dst, int E) {
    int i = blockIdx.x * blockDim.x + threadIdx.x;
    if (i < E) {
        atomicAdd(&g_deg_out[src[i]], 1);
        atomicAdd(&g_deg_in[dst[i]], 1);
    }
}

// K2: precompute W_fused = Wc @ Wa1  and bias = b_conv @ Wa1 + b_aggr
// grid = 129 blocks x 128 threads; block 128 does the bias row.
__global__ void fuse_kernel(const float* __restrict__ Wc,
                            const float* __restrict__ Wa,
                            const float* __restrict__ bc,
                            const float* __restrict__ ba) {
    int j = threadIdx.x;
    if (blockIdx.x < D) {
        int i = blockIdx.x;
        float s = 0.f;
#pragma unroll 8
        for (int k = 0; k < D; k++) s += Wc[i * D + k] * Wa[k * D + j];
        g_Wfused[i * D + j] = s;
    } else {
        float s = ba[j];
#pragma unroll 8
        for (int k = 0; k < D; k++) s += bc[k] * Wa[k * D + j];
        g_bias[j] = s;
    }
}

// K3: scatter-add: agg[dst[e]] += X[src[e]] * rsqrt(max(deg_out[src[e]],1))
// One warp per edge; each lane moves one float4 (full 512B row per warp).
__global__ __launch_bounds__(256) void scatter_kernel(
    const float4* __restrict__ X4,
    const int* __restrict__ src,
    const int* __restrict__ dst, int E) {
    int gt = blockIdx.x * 256 + threadIdx.x;
    int e = gt >> 5;
    int lane = gt & 31;
    if (e >= E) return;
    int s = __ldg(&src[e]);
    int d = __ldg(&dst[e]);
    float ns = rsqrtf(fmaxf((float)g_deg_out[s], 1.0f));
    float4 v = X4[s * 32 + lane];
    v.x *= ns; v.y *= ns; v.z *= ns; v.w *= ns;
    float4* p = ((float4*)g_agg) + d * 32 + lane;
    asm volatile("red.global.add.v4.f32 [%0], {%1,%2,%3,%4};"
                 :: "l"(p), "f"(v.x), "f"(v.y), "f"(v.z), "f"(v.w)
                 : "memory");
}

// K4: out = (agg * nd) @ W_fused + X @ Wa2 + bias
// Block: 256 threads = 8 warps; tile = 32 rows x 128 cols.
// Thread (warp w, lane l) owns rows {w, w+8, w+16, w+24}, cols [4l, 4l+4).
// smem: Ws 128x128 f32 (64KB) + Xs 32x128 f32 (16KB) = 80KB dynamic.
__global__ __launch_bounds__(256) void out_gemm_kernel(
    const float* __restrict__ X,
    const float* __restrict__ Wa2,   // = W_aggr + 128*128
    float* __restrict__ out, int n) {
    extern __shared__ float sm[];
    float* Ws = sm;            // 16384 floats
    float* Xs = sm + D * D;    // 4096 floats

    int row0 = blockIdx.x * 32;
    int l = threadIdx.x & 31;
    int w = threadIdx.x >> 5;

    float4 a0 = make_float4(0.f,0.f,0.f,0.f);
    float4 a1 = a0, a2 = a0, a3 = a0;

    for (int phase = 0; phase < 2; phase++) {
        const float* Wsrc = (phase == 0) ? g_Wfused : Wa2;
        // stage W (4096 float4 / 256 threads = 16 each)
        const float4* Wg4 = (const float4*)Wsrc;
#pragma unroll
        for (int i = threadIdx.x; i < D * D / 4; i += 256)
            ((float4*)Ws)[i] = Wg4[i];
        // stage A tile (1024 float4 / 256 threads = 4 each)
        for (int i = threadIdx.x; i < 32 * D / 4; i += 256) {
            int rl = i >> 5;
            int r = row0 + rl;
            float4 v = make_float4(0.f,0.f,0.f,0.f);
            if (r < n) {
                if (phase == 0) {
                    v = ((const float4*)g_agg)[r * 32 + (i & 31)];
                    float nd = rsqrtf(fmaxf((float)g_deg_in[r], 1.0f));
                    v.x *= nd; v.y *= nd; v.z *= nd; v.w *= nd;
                } else {
                    v = ((const float4*)X)[r * 32 + (i & 31)];
                }
            }
            ((float4*)Xs)[i] = v;
        }
        __syncthreads();

        const float4* Ws4 = (const float4*)Ws;
#pragma unroll 4
        for (int k = 0; k < D; k++) {
            float4 wv = Ws4[k * 32 + l];
            float x0 = Xs[(w     ) * D + k];
            float x1 = Xs[(w +  8) * D + k];
            float x2 = Xs[(w + 16) * D + k];
            float x3 = Xs[(w + 24) * D + k];
            a0.x += x0 * wv.x; a0.y += x0 * wv.y; a0.z += x0 * wv.z; a0.w += x0 * wv.w;
            a1.x += x1 * wv.x; a1.y += x1 * wv.y; a1.z += x1 * wv.z; a1.w += x1 * wv.w;
            a2.x += x2 * wv.x; a2.y += x2 * wv.y; a2.z += x2 * wv.z; a2.w += x2 * wv.w;
            a3.x += x3 * wv.x; a3.y += x3 * wv.y; a3.z += x3 * wv.z; a3.w += x3 * wv.w;
        }
        __syncthreads();
    }

    float4 bv = ((const float4*)g_bias)[l];
    a0.x += bv.x; a0.y += bv.y; a0.z += bv.z; a0.w += bv.w;
    a1.x += bv.x; a1.y += bv.y; a1.z += bv.z; a1.w += bv.w;
    a2.x += bv.x; a2.y += bv.y; a2.z += bv.z; a2.w += bv.w;
    a3.x += bv.x; a3.y += bv.y; a3.z += bv.z; a3.w += bv.w;

    float4* out4 = (float4*)out;
    int r;
    r = row0 + w;      if (r < n) out4[r * 32 + l] = a0;
    r = row0 + w + 8;  if (r < n) out4[r * 32 + l] = a1;
    r = row0 + w + 16; if (r < n) out4[r * 32 + l] = a2;
    r = row0 + w + 24; if (r < n) out4[r * 32 + l] = a3;
}

// ---------------------------------------------------------------------------
extern "C" void kernel_launch(void* const* d_in, const int* in_sizes, int n_in,
                              void* d_out, int out_size) {
    const float* features = (const float*)d_in[0];
    const int*   src      = (const int*)d_in[1];
    const int*   dst      = (const int*)d_in[2];
    const float* W_conv   = (const float*)d_in[3];
    const float* b_conv   = (const float*)d_in[4];
    const float* W_aggr   = (const float*)d_in[5];
    const float* b_aggr   = (const float*)d_in[6];
    float* out = (float*)d_out;

    int n = in_sizes[0] / D;
    int E = in_sizes[1];

    static int smem_set = 0;
    (void)smem_set;
    cudaFuncSetAttribute(out_gemm_kernel,
                         cudaFuncAttributeMaxDynamicSharedMemorySize,
                         (D * D + 32 * D) * (int)sizeof(float));

    int nf4 = n * (D / 4);
    zero_kernel<<<(nf4 + 255) / 256, 256>>>(n);
    deg_kernel<<<(E + 255) / 256, 256>>>(src, dst, E);
    fuse_kernel<<<D + 1, D>>>(W_conv, W_aggr, b_conv, b_aggr);

    long long threads = (long long)E * 32;
    scatter_kernel<<<(int)((threads + 255) / 256), 256>>>(
        (const float4*)features, src, dst, E);

    int smem = (D * D + 32 * D) * (int)sizeof(float);
    out_gemm_kernel<<<(n + 31) / 32, 256, smem>>>(
        features, W_aggr + D * D, out, n);
}